// round 1
// baseline (speedup 1.0000x reference)
#include <cuda_runtime.h>

// SSIM loss, fused single kernel.
// img1, img2: [16,3,512,512] fp32. Output: scalar mean of SSIM map.

constexpr int IMG_H = 512;
constexpr int IMG_W = 512;
constexpr int NPLANES = 48;          // 16 * 3
constexpr int TILE = 64;
constexpr int HALO = 5;
constexpr int IN = TILE + 2 * HALO;  // 74
constexpr int IMG_STRIDE = 76;       // padded row stride for image tiles (mult of 4)
constexpr int H_STRIDE = 68;         // padded row stride for H arrays (mult of 4)
constexpr int MAPSZ = IN * H_STRIDE; // one horizontal-conv map
constexpr int NTHREADS = 512;
constexpr int SMEM_FLOATS = 2 * IN * IMG_STRIDE + 5 * MAPSZ;
constexpr float C1f = 0.0001f;       // 0.01^2
constexpr float C2f = 0.0009f;       // 0.03^2

// Gaussian(sigma=1.5) 1D weights, normalized (separable: w2d = outer(g,g))
__device__ constexpr float G[11] = {
    0.00102838f, 0.00759876f, 0.03600077f, 0.10936070f, 0.21300460f,
    0.26601170f,
    0.21300460f, 0.10936070f, 0.03600077f, 0.00759876f, 0.00102838f
};

__device__ double g_accum;

__global__ void ssim_zero_kernel() { g_accum = 0.0; }

__global__ void ssim_final_kernel(float* __restrict__ out) {
    out[0] = (float)(g_accum / (double)(16.0 * 3.0 * 512.0 * 512.0));
}

// 11-tap horizontal conv of an 18-float window -> 8 outputs (weights fold to FFMA-imm)
__device__ __forceinline__ void conv_row8(const float* __restrict__ w, float* __restrict__ acc) {
#pragma unroll
    for (int k = 0; k < 8; k++) {
        float s = 0.f;
#pragma unroll
        for (int j = 0; j < 11; j++) s = fmaf(G[j], w[k + j], s);
        acc[k] = s;
    }
}

__device__ __forceinline__ void store8(float* __restrict__ p, const float* __restrict__ acc) {
    float4* q = reinterpret_cast<float4*>(p);
    q[0] = make_float4(acc[0], acc[1], acc[2], acc[3]);
    q[1] = make_float4(acc[4], acc[5], acc[6], acc[7]);
}

__global__ void __launch_bounds__(NTHREADS, 1)
ssim_main_kernel(const float* __restrict__ img1, const float* __restrict__ img2) {
    extern __shared__ float sm[];
    float* s1 = sm;                          // [IN][IMG_STRIDE]
    float* s2 = sm + IN * IMG_STRIDE;        // [IN][IMG_STRIDE]
    float* sH = sm + 2 * IN * IMG_STRIDE;    // [5][IN][H_STRIDE]: mu1,mu2,x2,y2,xy

    const int tid = threadIdx.x;
    const int plane = blockIdx.z;
    const int ty = blockIdx.y * TILE;
    const int tx = blockIdx.x * TILE;
    const float* p1 = img1 + (size_t)plane * IMG_H * IMG_W;
    const float* p2 = img2 + (size_t)plane * IMG_H * IMG_W;

    // ---- Phase 1: load input tiles (with zero halo) ----
    for (int i = tid; i < IN * IN; i += NTHREADS) {
        int r = i / IN, c = i - r * IN;
        int gy = ty + r - HALO, gx = tx + c - HALO;
        float v1 = 0.f, v2 = 0.f;
        if (((unsigned)gy < (unsigned)IMG_H) & ((unsigned)gx < (unsigned)IMG_W)) {
            int gi = gy * IMG_W + gx;
            v1 = __ldg(p1 + gi);
            v2 = __ldg(p2 + gi);
        }
        s1[r * IMG_STRIDE + c] = v1;
        s2[r * IMG_STRIDE + c] = v2;
    }
    __syncthreads();

    // ---- Phase 2: horizontal conv of 5 maps; each task = 1 row x 8-col octet ----
    for (int t = tid; t < IN * 8; t += NTHREADS) {
        int r = t >> 3;
        int c0 = (t & 7) * 8;
        float wa[20], wb[20];
        const float4* a4 = reinterpret_cast<const float4*>(s1 + r * IMG_STRIDE + c0);
        const float4* b4 = reinterpret_cast<const float4*>(s2 + r * IMG_STRIDE + c0);
#pragma unroll
        for (int i = 0; i < 5; i++) {
            float4 va = a4[i];
            float4 vb = b4[i];
            wa[4 * i + 0] = va.x; wa[4 * i + 1] = va.y; wa[4 * i + 2] = va.z; wa[4 * i + 3] = va.w;
            wb[4 * i + 0] = vb.x; wb[4 * i + 1] = vb.y; wb[4 * i + 2] = vb.z; wb[4 * i + 3] = vb.w;
        }
        float* hrow = sH + r * H_STRIDE + c0;
        float acc[8];
        conv_row8(wa, acc);                       // mu1
        store8(hrow + 0 * MAPSZ, acc);
        conv_row8(wb, acc);                       // mu2
        store8(hrow + 1 * MAPSZ, acc);
        float p[20];
#pragma unroll
        for (int i = 0; i < 20; i++) p[i] = wa[i] * wb[i];
        conv_row8(p, acc);                        // x*y
        store8(hrow + 4 * MAPSZ, acc);
#pragma unroll
        for (int i = 0; i < 20; i++) p[i] = wa[i] * wa[i];
        conv_row8(p, acc);                        // x^2
        store8(hrow + 2 * MAPSZ, acc);
#pragma unroll
        for (int i = 0; i < 20; i++) p[i] = wb[i] * wb[i];
        conv_row8(p, acc);                        // y^2
        store8(hrow + 3 * MAPSZ, acc);
    }
    __syncthreads();

    // ---- Phase 3: vertical conv (8-row strip per thread) + SSIM + reduce ----
    float lsum = 0.f;
    {
        const int c = tid & 63;
        const int r0 = (tid >> 6) * 8;
        float am1[8], am2[8], ax2[8], ay2[8], axy[8];
#pragma unroll
        for (int k = 0; k < 8; k++) { am1[k] = 0.f; am2[k] = 0.f; ax2[k] = 0.f; ay2[k] = 0.f; axy[k] = 0.f; }
        const float* h0 = sH + 0 * MAPSZ + r0 * H_STRIDE + c;
        const float* h1 = sH + 1 * MAPSZ + r0 * H_STRIDE + c;
        const float* h2 = sH + 2 * MAPSZ + r0 * H_STRIDE + c;
        const float* h3 = sH + 3 * MAPSZ + r0 * H_STRIDE + c;
        const float* h4 = sH + 4 * MAPSZ + r0 * H_STRIDE + c;
#pragma unroll
        for (int i = 0; i < 18; i++) {
            float v0 = h0[i * H_STRIDE];
            float v1 = h1[i * H_STRIDE];
            float v2 = h2[i * H_STRIDE];
            float v3 = h3[i * H_STRIDE];
            float v4 = h4[i * H_STRIDE];
#pragma unroll
            for (int ro = 0; ro < 8; ro++) {
                const int j = i - ro;
                if (j >= 0 && j < 11) {
                    am1[ro] = fmaf(G[j], v0, am1[ro]);
                    am2[ro] = fmaf(G[j], v1, am2[ro]);
                    ax2[ro] = fmaf(G[j], v2, ax2[ro]);
                    ay2[ro] = fmaf(G[j], v3, ay2[ro]);
                    axy[ro] = fmaf(G[j], v4, axy[ro]);
                }
            }
        }
#pragma unroll
        for (int ro = 0; ro < 8; ro++) {
            float mu1 = am1[ro], mu2 = am2[ro];
            float mu11 = mu1 * mu1, mu22 = mu2 * mu2, mu12 = mu1 * mu2;
            float sx = ax2[ro] - mu11;
            float sy = ay2[ro] - mu22;
            float sxy = axy[ro] - mu12;
            float num = (2.f * mu12 + C1f) * (2.f * sxy + C2f);
            float den = (mu11 + mu22 + C1f) * (sx + sy + C2f);
            lsum += __fdividef(num, den);
        }
    }

    // block reduce
#pragma unroll
    for (int o = 16; o > 0; o >>= 1) lsum += __shfl_xor_sync(0xFFFFFFFFu, lsum, o);
    __shared__ float wsum[NTHREADS / 32];
    if ((tid & 31) == 0) wsum[tid >> 5] = lsum;
    __syncthreads();
    if (tid == 0) {
        float s = 0.f;
#pragma unroll
        for (int i = 0; i < NTHREADS / 32; i++) s += wsum[i];
        atomicAdd(&g_accum, (double)s);
    }
}

extern "C" void kernel_launch(void* const* d_in, const int* in_sizes, int n_in,
                              void* d_out, int out_size) {
    const float* img1 = (const float*)d_in[0];
    const float* img2 = (const float*)d_in[1];
    float* out = (float*)d_out;

    cudaFuncSetAttribute(ssim_main_kernel,
                         cudaFuncAttributeMaxDynamicSharedMemorySize,
                         SMEM_FLOATS * (int)sizeof(float));

    ssim_zero_kernel<<<1, 1>>>();
    dim3 grid(IMG_W / TILE, IMG_H / TILE, NPLANES);
    ssim_main_kernel<<<grid, NTHREADS, SMEM_FLOATS * sizeof(float)>>>(img1, img2);
    ssim_final_kernel<<<1, 1>>>(out);
}

// round 2
// speedup vs baseline: 1.1279x; 1.1279x over previous
#include <cuda_runtime.h>

// SSIM loss, fully fused single kernel (separable 11-tap Gaussian).
// img1, img2: [16,3,512,512] fp32. Output: scalar mean of SSIM map.

constexpr int IMG_H = 512;
constexpr int IMG_W = 512;
constexpr int NPLANES = 48;            // 16 * 3
constexpr int TILE = 64;
constexpr int HALO = 5;
constexpr int IN = TILE + 2 * HALO;    // 74
constexpr int IMG_STRIDE = 76;         // padded row stride for image tiles
constexpr int H_STRIDE = 64;           // row stride for H-conv maps (64 output cols)
constexpr int MAPSZ = IN * H_STRIDE;   // 4736
constexpr int NTHREADS = 1024;
constexpr int GRID_X = IMG_W / TILE;   // 8
constexpr int GRID_Y = IMG_H / TILE;   // 8
constexpr int NBLOCKS = GRID_X * GRID_Y * NPLANES;  // 3072
constexpr int NT2 = IN * 8;            // 592 row-octets
constexpr int SMEM_FLOATS = 2 * IN * IMG_STRIDE + 5 * MAPSZ;  // 34928 (~140KB)
constexpr float C1f = 0.0001f;
constexpr float C2f = 0.0009f;

// Gaussian(sigma=1.5) 1D weights, normalized (w2d = outer(g,g))
__device__ constexpr float G[11] = {
    0.00102838f, 0.00759876f, 0.03600077f, 0.10936070f, 0.21300460f,
    0.26601170f,
    0.21300460f, 0.10936070f, 0.03600077f, 0.00759876f, 0.00102838f
};

__device__ float g_partial[NBLOCKS];
__device__ unsigned int g_count;   // starts 0 (BSS), self-resets each call

// 11-tap horizontal conv of an 18-float window -> 8 outputs (weights fold to FFMA-imm)
__device__ __forceinline__ void conv_row8(const float* __restrict__ w, float* __restrict__ acc) {
#pragma unroll
    for (int k = 0; k < 8; k++) {
        float s = 0.f;
#pragma unroll
        for (int j = 0; j < 11; j++) s = fmaf(G[j], w[k + j], s);
        acc[k] = s;
    }
}

__device__ __forceinline__ void load20(const float* __restrict__ src, float* __restrict__ w) {
    const float4* s4 = reinterpret_cast<const float4*>(src);
#pragma unroll
    for (int i = 0; i < 5; i++) {
        float4 v = s4[i];
        w[4 * i + 0] = v.x; w[4 * i + 1] = v.y; w[4 * i + 2] = v.z; w[4 * i + 3] = v.w;
    }
}

__device__ __forceinline__ void store8(float* __restrict__ p, const float* __restrict__ acc) {
    float4* q = reinterpret_cast<float4*>(p);
    q[0] = make_float4(acc[0], acc[1], acc[2], acc[3]);
    q[1] = make_float4(acc[4], acc[5], acc[6], acc[7]);
}

__global__ void __launch_bounds__(NTHREADS, 1)
ssim_main_kernel(const float* __restrict__ img1, const float* __restrict__ img2,
                 float* __restrict__ out) {
    extern __shared__ float sm[];
    float* s1 = sm;                          // [IN][IMG_STRIDE]
    float* s2 = sm + IN * IMG_STRIDE;
    float* sH = sm + 2 * IN * IMG_STRIDE;    // [5][IN][H_STRIDE]: mu1,mu2,x2,y2,xy

    const int tid = threadIdx.x;
    const int plane = blockIdx.z;
    const int ty = blockIdx.y * TILE;
    const int tx = blockIdx.x * TILE;
    const float* p1 = img1 + (size_t)plane * IMG_H * IMG_W;
    const float* p2 = img2 + (size_t)plane * IMG_H * IMG_W;

    // ---- Phase 1: load input tiles (zero halo at image edges) ----
    for (int i = tid; i < IN * IN; i += NTHREADS) {
        int r = i / IN, c = i - r * IN;
        int gy = ty + r - HALO, gx = tx + c - HALO;
        float v1 = 0.f, v2 = 0.f;
        if (((unsigned)gy < (unsigned)IMG_H) & ((unsigned)gx < (unsigned)IMG_W)) {
            int gi = gy * IMG_W + gx;
            v1 = __ldg(p1 + gi);
            v2 = __ldg(p2 + gi);
        }
        s1[r * IMG_STRIDE + c] = v1;
        s2[r * IMG_STRIDE + c] = v2;
    }
    __syncthreads();

    // ---- Phase 2: horizontal conv of 5 maps.
    // Task = (row-octet, group). group 0: mu1+x2 from img1; group 1: mu2+y2 from img2;
    // group 2: xy from both. 1776 tasks / 1024 threads, max ~50 live regs per task.
    for (int t = tid; t < NT2 * 3; t += NTHREADS) {
        int ro = t % NT2;
        int g = t / NT2;
        int r = ro >> 3;
        int c0 = (ro & 7) << 3;
        float* hrow = sH + r * H_STRIDE + c0;
        float acc[8];
        if (g == 0) {
            float w[20];
            load20(s1 + r * IMG_STRIDE + c0, w);
            conv_row8(w, acc);
            store8(hrow + 0 * MAPSZ, acc);            // mu1
#pragma unroll
            for (int i = 0; i < 18; i++) w[i] = w[i] * w[i];
            conv_row8(w, acc);
            store8(hrow + 2 * MAPSZ, acc);            // x^2
        } else if (g == 1) {
            float w[20];
            load20(s2 + r * IMG_STRIDE + c0, w);
            conv_row8(w, acc);
            store8(hrow + 1 * MAPSZ, acc);            // mu2
#pragma unroll
            for (int i = 0; i < 18; i++) w[i] = w[i] * w[i];
            conv_row8(w, acc);
            store8(hrow + 3 * MAPSZ, acc);            // y^2
        } else {
            float wa[20], wb[20];
            load20(s1 + r * IMG_STRIDE + c0, wa);
            load20(s2 + r * IMG_STRIDE + c0, wb);
#pragma unroll
            for (int i = 0; i < 18; i++) wa[i] = wa[i] * wb[i];
            conv_row8(wa, acc);
            store8(hrow + 4 * MAPSZ, acc);            // x*y
        }
    }
    __syncthreads();

    // ---- Phase 3: vertical conv (4-row strip per thread, exactly 1024 tasks) ----
    float lsum = 0.f;
    {
        const int c = tid & 63;
        const int r0 = (tid >> 6) * 4;                // 16 strips of 4 rows
        float am1[4], am2[4], ax2[4], ay2[4], axy[4];
#pragma unroll
        for (int k = 0; k < 4; k++) { am1[k] = 0.f; am2[k] = 0.f; ax2[k] = 0.f; ay2[k] = 0.f; axy[k] = 0.f; }
        const float* h0 = sH + 0 * MAPSZ + r0 * H_STRIDE + c;
        const float* h1 = sH + 1 * MAPSZ + r0 * H_STRIDE + c;
        const float* h2 = sH + 2 * MAPSZ + r0 * H_STRIDE + c;
        const float* h3 = sH + 3 * MAPSZ + r0 * H_STRIDE + c;
        const float* h4 = sH + 4 * MAPSZ + r0 * H_STRIDE + c;
#pragma unroll
        for (int i = 0; i < 14; i++) {
            float v0 = h0[i * H_STRIDE];
            float v1 = h1[i * H_STRIDE];
            float v2 = h2[i * H_STRIDE];
            float v3 = h3[i * H_STRIDE];
            float v4 = h4[i * H_STRIDE];
#pragma unroll
            for (int ro = 0; ro < 4; ro++) {
                const int j = i - ro;
                if (j >= 0 && j < 11) {
                    am1[ro] = fmaf(G[j], v0, am1[ro]);
                    am2[ro] = fmaf(G[j], v1, am2[ro]);
                    ax2[ro] = fmaf(G[j], v2, ax2[ro]);
                    ay2[ro] = fmaf(G[j], v3, ay2[ro]);
                    axy[ro] = fmaf(G[j], v4, axy[ro]);
                }
            }
        }
#pragma unroll
        for (int ro = 0; ro < 4; ro++) {
            float mu1 = am1[ro], mu2 = am2[ro];
            float mu11 = mu1 * mu1, mu22 = mu2 * mu2, mu12 = mu1 * mu2;
            float sx = ax2[ro] - mu11;
            float sy = ay2[ro] - mu22;
            float sxy = axy[ro] - mu12;
            float num = (2.f * mu12 + C1f) * (2.f * sxy + C2f);
            float den = (mu11 + mu22 + C1f) * (sx + sy + C2f);
            lsum += num / den;
        }
    }

    // ---- Block reduce (fp32) ----
    __shared__ float wsum[NTHREADS / 32];
#pragma unroll
    for (int o = 16; o > 0; o >>= 1) lsum += __shfl_xor_sync(0xFFFFFFFFu, lsum, o);
    if ((tid & 31) == 0) wsum[tid >> 5] = lsum;
    __syncthreads();

    const int bid = (blockIdx.z * GRID_Y + blockIdx.y) * GRID_X + blockIdx.x;
    __shared__ bool isLast;
    if (tid == 0) {
        float s = 0.f;
#pragma unroll
        for (int i = 0; i < NTHREADS / 32; i++) s += wsum[i];
        g_partial[bid] = s;
        __threadfence();
        unsigned int old = atomicAdd(&g_count, 1u);
        isLast = (old == (unsigned)(NBLOCKS - 1));
    }
    __syncthreads();

    // ---- Last block: final reduction in double ----
    if (isLast) {
        double d = 0.0;
#pragma unroll
        for (int k = 0; k < NBLOCKS / NTHREADS; k++)
            d += (double)g_partial[tid + k * NTHREADS];
#pragma unroll
        for (int o = 16; o > 0; o >>= 1) d += __shfl_xor_sync(0xFFFFFFFFu, d, o);
        __shared__ double dsum[NTHREADS / 32];
        if ((tid & 31) == 0) dsum[tid >> 5] = d;
        __syncthreads();
        if (tid == 0) {
            double s = 0.0;
#pragma unroll
            for (int i = 0; i < NTHREADS / 32; i++) s += dsum[i];
            out[0] = (float)(s / (double)((size_t)NPLANES * IMG_H * IMG_W));
            g_count = 0;   // self-reset for next graph replay
        }
    }
}

extern "C" void kernel_launch(void* const* d_in, const int* in_sizes, int n_in,
                              void* d_out, int out_size) {
    const float* img1 = (const float*)d_in[0];
    const float* img2 = (const float*)d_in[1];
    float* out = (float*)d_out;

    cudaFuncSetAttribute(ssim_main_kernel,
                         cudaFuncAttributeMaxDynamicSharedMemorySize,
                         SMEM_FLOATS * (int)sizeof(float));

    dim3 grid(GRID_X, GRID_Y, NPLANES);
    ssim_main_kernel<<<grid, NTHREADS, SMEM_FLOATS * sizeof(float)>>>(img1, img2, out);
}

// round 3
// speedup vs baseline: 1.1400x; 1.0107x over previous
#include <cuda_runtime.h>

// SSIM loss, fully fused single kernel (separable 11-tap Gaussian).
// img1, img2: [16,3,512,512] fp32. Output: scalar mean of SSIM map.
// R3: 2 CTAs x 512 threads per SM (64x32 tiles) to overlap barrier stalls.

constexpr int IMG_H = 512;
constexpr int IMG_W = 512;
constexpr int NPLANES = 48;              // 16 * 3
constexpr int TILE_W = 64;
constexpr int TILE_H = 32;
constexpr int HALO = 5;
constexpr int IN_W = TILE_W + 2 * HALO;  // 74
constexpr int IN_H = TILE_H + 2 * HALO;  // 42
constexpr int IMG_STRIDE = 76;           // padded row stride for input tiles
constexpr int H_STRIDE = 64;             // row stride for H-conv maps
constexpr int MAPSZ = IN_H * H_STRIDE;   // 2688
constexpr int NTHREADS = 512;
constexpr int GRID_X = IMG_W / TILE_W;   // 8
constexpr int GRID_Y = IMG_H / TILE_H;   // 16
constexpr int NBLOCKS = GRID_X * GRID_Y * NPLANES;  // 6144
constexpr int NT2 = IN_H * 8;            // 336 row-octets
constexpr int SMEM_FLOATS = 2 * IN_H * IMG_STRIDE + 5 * MAPSZ;  // 19824 (~79KB)
constexpr float C1f = 0.0001f;
constexpr float C2f = 0.0009f;

// Gaussian(sigma=1.5) 1D weights, normalized (w2d = outer(g,g))
__device__ constexpr float G[11] = {
    0.00102838f, 0.00759876f, 0.03600077f, 0.10936070f, 0.21300460f,
    0.26601170f,
    0.21300460f, 0.10936070f, 0.03600077f, 0.00759876f, 0.00102838f
};

__device__ float g_partial[NBLOCKS];
__device__ unsigned int g_count;   // starts 0 (BSS), self-resets each call

// 11-tap horizontal conv of an 18-float window -> 8 outputs (weights fold to FFMA-imm)
__device__ __forceinline__ void conv_row8(const float* __restrict__ w, float* __restrict__ acc) {
#pragma unroll
    for (int k = 0; k < 8; k++) {
        float s = 0.f;
#pragma unroll
        for (int j = 0; j < 11; j++) s = fmaf(G[j], w[k + j], s);
        acc[k] = s;
    }
}

__device__ __forceinline__ void load20(const float* __restrict__ src, float* __restrict__ w) {
    const float4* s4 = reinterpret_cast<const float4*>(src);
#pragma unroll
    for (int i = 0; i < 5; i++) {
        float4 v = s4[i];
        w[4 * i + 0] = v.x; w[4 * i + 1] = v.y; w[4 * i + 2] = v.z; w[4 * i + 3] = v.w;
    }
}

__device__ __forceinline__ void store8(float* __restrict__ p, const float* __restrict__ acc) {
    float4* q = reinterpret_cast<float4*>(p);
    q[0] = make_float4(acc[0], acc[1], acc[2], acc[3]);
    q[1] = make_float4(acc[4], acc[5], acc[6], acc[7]);
}

__global__ void __launch_bounds__(NTHREADS, 2)
ssim_main_kernel(const float* __restrict__ img1, const float* __restrict__ img2,
                 float* __restrict__ out) {
    extern __shared__ float sm[];
    float* s1 = sm;                           // [IN_H][IMG_STRIDE]
    float* s2 = sm + IN_H * IMG_STRIDE;
    float* sH = sm + 2 * IN_H * IMG_STRIDE;   // [5][IN_H][H_STRIDE]: mu1,mu2,x2,y2,xy

    const int tid = threadIdx.x;
    const int plane = blockIdx.z;
    const int ty = blockIdx.y * TILE_H;
    const int tx = blockIdx.x * TILE_W;
    const float* p1 = img1 + (size_t)plane * IMG_H * IMG_W;
    const float* p2 = img2 + (size_t)plane * IMG_H * IMG_W;

    // ---- Phase 1: load input tiles (zero halo at image edges) ----
    for (int i = tid; i < IN_H * IN_W; i += NTHREADS) {
        int r = i / IN_W, c = i - r * IN_W;
        int gy = ty + r - HALO, gx = tx + c - HALO;
        float v1 = 0.f, v2 = 0.f;
        if (((unsigned)gy < (unsigned)IMG_H) & ((unsigned)gx < (unsigned)IMG_W)) {
            int gi = gy * IMG_W + gx;
            v1 = __ldg(p1 + gi);
            v2 = __ldg(p2 + gi);
        }
        s1[r * IMG_STRIDE + c] = v1;
        s2[r * IMG_STRIDE + c] = v2;
    }
    __syncthreads();

    // ---- Phase 2: horizontal conv of 5 maps.
    // Task = (row-octet, group). group 0: mu1+x2; group 1: mu2+y2; group 2: xy.
    // 1008 tasks / 512 threads.
    for (int t = tid; t < NT2 * 3; t += NTHREADS) {
        int ro = t % NT2;
        int g = t / NT2;
        int r = ro >> 3;
        int c0 = (ro & 7) << 3;
        float* hrow = sH + r * H_STRIDE + c0;
        float acc[8];
        if (g == 0) {
            float w[20];
            load20(s1 + r * IMG_STRIDE + c0, w);
            conv_row8(w, acc);
            store8(hrow + 0 * MAPSZ, acc);            // mu1
#pragma unroll
            for (int i = 0; i < 18; i++) w[i] = w[i] * w[i];
            conv_row8(w, acc);
            store8(hrow + 2 * MAPSZ, acc);            // x^2
        } else if (g == 1) {
            float w[20];
            load20(s2 + r * IMG_STRIDE + c0, w);
            conv_row8(w, acc);
            store8(hrow + 1 * MAPSZ, acc);            // mu2
#pragma unroll
            for (int i = 0; i < 18; i++) w[i] = w[i] * w[i];
            conv_row8(w, acc);
            store8(hrow + 3 * MAPSZ, acc);            // y^2
        } else {
            float wa[20], wb[20];
            load20(s1 + r * IMG_STRIDE + c0, wa);
            load20(s2 + r * IMG_STRIDE + c0, wb);
#pragma unroll
            for (int i = 0; i < 18; i++) wa[i] = wa[i] * wb[i];
            conv_row8(wa, acc);
            store8(hrow + 4 * MAPSZ, acc);            // x*y
        }
    }
    __syncthreads();

    // ---- Phase 3: vertical conv (4-row strip per thread, exactly 512 tasks) ----
    float lsum = 0.f;
    {
        const int c = tid & 63;
        const int r0 = (tid >> 6) * 4;                // 8 strips of 4 rows
        float am1[4], am2[4], ax2[4], ay2[4], axy[4];
#pragma unroll
        for (int k = 0; k < 4; k++) { am1[k] = 0.f; am2[k] = 0.f; ax2[k] = 0.f; ay2[k] = 0.f; axy[k] = 0.f; }
        const float* h0 = sH + 0 * MAPSZ + r0 * H_STRIDE + c;
        const float* h1 = sH + 1 * MAPSZ + r0 * H_STRIDE + c;
        const float* h2 = sH + 2 * MAPSZ + r0 * H_STRIDE + c;
        const float* h3 = sH + 3 * MAPSZ + r0 * H_STRIDE + c;
        const float* h4 = sH + 4 * MAPSZ + r0 * H_STRIDE + c;
#pragma unroll
        for (int i = 0; i < 14; i++) {
            float v0 = h0[i * H_STRIDE];
            float v1 = h1[i * H_STRIDE];
            float v2 = h2[i * H_STRIDE];
            float v3 = h3[i * H_STRIDE];
            float v4 = h4[i * H_STRIDE];
#pragma unroll
            for (int ro = 0; ro < 4; ro++) {
                const int j = i - ro;
                if (j >= 0 && j < 11) {
                    am1[ro] = fmaf(G[j], v0, am1[ro]);
                    am2[ro] = fmaf(G[j], v1, am2[ro]);
                    ax2[ro] = fmaf(G[j], v2, ax2[ro]);
                    ay2[ro] = fmaf(G[j], v3, ay2[ro]);
                    axy[ro] = fmaf(G[j], v4, axy[ro]);
                }
            }
        }
#pragma unroll
        for (int ro = 0; ro < 4; ro++) {
            float mu1 = am1[ro], mu2 = am2[ro];
            float mu11 = mu1 * mu1, mu22 = mu2 * mu2, mu12 = mu1 * mu2;
            float sx = ax2[ro] - mu11;
            float sy = ay2[ro] - mu22;
            float sxy = axy[ro] - mu12;
            float num = (2.f * mu12 + C1f) * (2.f * sxy + C2f);
            float den = (mu11 + mu22 + C1f) * (sx + sy + C2f);
            lsum += num / den;
        }
    }

    // ---- Block reduce (fp32) ----
    __shared__ float wsum[NTHREADS / 32];
#pragma unroll
    for (int o = 16; o > 0; o >>= 1) lsum += __shfl_xor_sync(0xFFFFFFFFu, lsum, o);
    if ((tid & 31) == 0) wsum[tid >> 5] = lsum;
    __syncthreads();

    const int bid = (blockIdx.z * GRID_Y + blockIdx.y) * GRID_X + blockIdx.x;
    __shared__ bool isLast;
    if (tid == 0) {
        float s = 0.f;
#pragma unroll
        for (int i = 0; i < NTHREADS / 32; i++) s += wsum[i];
        g_partial[bid] = s;
        __threadfence();
        unsigned int old = atomicAdd(&g_count, 1u);
        isLast = (old == (unsigned)(NBLOCKS - 1));
    }
    __syncthreads();

    // ---- Last block: final reduction in double ----
    if (isLast) {
        double d = 0.0;
#pragma unroll
        for (int k = 0; k < NBLOCKS / NTHREADS; k++)
            d += (double)g_partial[tid + k * NTHREADS];
#pragma unroll
        for (int o = 16; o > 0; o >>= 1) d += __shfl_xor_sync(0xFFFFFFFFu, d, o);
        __shared__ double dsum[NTHREADS / 32];
        if ((tid & 31) == 0) dsum[tid >> 5] = d;
        __syncthreads();
        if (tid == 0) {
            double s = 0.0;
#pragma unroll
            for (int i = 0; i < NTHREADS / 32; i++) s += dsum[i];
            out[0] = (float)(s / (double)((size_t)NPLANES * IMG_H * IMG_W));
            g_count = 0;   // self-reset for next graph replay
        }
    }
}

extern "C" void kernel_launch(void* const* d_in, const int* in_sizes, int n_in,
                              void* d_out, int out_size) {
    const float* img1 = (const float*)d_in[0];
    const float* img2 = (const float*)d_in[1];
    float* out = (float*)d_out;

    cudaFuncSetAttribute(ssim_main_kernel,
                         cudaFuncAttributeMaxDynamicSharedMemorySize,
                         SMEM_FLOATS * (int)sizeof(float));

    dim3 grid(GRID_X, GRID_Y, NPLANES);
    ssim_main_kernel<<<grid, NTHREADS, SMEM_FLOATS * sizeof(float)>>>(img1, img2, out);
}